// round 10
// baseline (speedup 1.0000x reference)
#include <cuda_runtime.h>

// Problem constants
#define N_ROWS   1344              // B*C = 64*21
#define R_WIN    32                // windows per row (L/MAX_PL = 1024/32)
#define NWIN     (N_ROWS * R_WIN)  // 43008
#define DM       512               // D_MODEL
#define TGT      4                 // MAX_PL/MIN_PL
#define PE_LEN   128               // R_WIN * TGT
#define MAIN_OUT ((long long)N_ROWS * PE_LEN * DM)  // 88080384
#define CLS_BLOCKS (NWIN / 128)    // 336 blocks x 128 threads (1 thread/window)

typedef unsigned long long u64;

// f32x2 packed helpers (sm_103a FFMA2 — PTX-only form).
__device__ __forceinline__ u64 fma2(u64 a, u64 b, u64 c) {
    u64 d; asm("fma.rn.f32x2 %0, %1, %2, %3;" : "=l"(d) : "l"(a), "l"(b), "l"(c));
    return d;
}
__device__ __forceinline__ u64 mul2(u64 a, u64 b) {
    u64 d; asm("mul.rn.f32x2 %0, %1, %2;" : "=l"(d) : "l"(a), "l"(b));
    return d;
}
__device__ __forceinline__ u64 add2(u64 a, u64 b) {
    u64 d; asm("add.rn.f32x2 %0, %1, %2;" : "=l"(d) : "l"(a), "l"(b));
    return d;
}
__device__ __forceinline__ float hadd2(u64 a) {
    float lo, hi;
    asm("mov.b64 {%0, %1}, %2;" : "=f"(lo), "=f"(hi) : "l"(a));
    return lo + hi;
}

// Scratch: packed preds, 2 bits per window via two ballot words per n.
__device__ uint2 g_predpk[N_ROWS];

// ---------------------------------------------------------------------------
// Kernel 1: classifier + tail fill. One thread per window, weights staged in
// smem (broadcast LDS inner loop). Each warp covers exactly one n's 32
// windows -> preds packed via two ballots, one uint2 store per n.
// ---------------------------------------------------------------------------
__global__ void __launch_bounds__(128)
pre_kernel(const float* __restrict__ x,
           const float* __restrict__ w1,
           const float* __restrict__ b1,
           const float* __restrict__ w2,
           const float* __restrict__ b2,
           float* __restrict__ out,
           long long tail_start, long long total) {
    int bid = blockIdx.x;
    if (bid >= CLS_BLOCKS) {
        long long i = tail_start + (long long)(bid - CLS_BLOCKS) * 128 + threadIdx.x;
        if (i < total) out[i] = 21.0f;   // reference returns (x_patch, C=21)
        return;
    }

    __shared__ __align__(16) float s_w1[64 * 32];   // 8 KB
    __shared__ __align__(16) float s_w2[192];
    __shared__ float s_b1[64];
    __shared__ float s_b2[3];

    const int tid = threadIdx.x;

    // Cooperative coalesced staging.
    {
        const float4* g = (const float4*)w1;
        float4* sm = (float4*)s_w1;
#pragma unroll
        for (int i = 0; i < 4; i++) sm[tid + 128 * i] = g[tid + 128 * i];
        if (tid < 48) ((float4*)s_w2)[tid] = ((const float4*)w2)[tid];
        if (tid < 64) s_b1[tid] = b1[tid];
        if (tid < 3)  s_b2[tid] = b2[tid];
    }
    __syncthreads();

    const int w = bid * 128 + tid;

    const float4* xw = (const float4*)(x + (size_t)w * 32);
    float4 xv[8];
#pragma unroll
    for (int i = 0; i < 8; i++) xv[i] = xw[i];

    float l0 = s_b2[0], l1 = s_b2[1], l2 = s_b2[2];

#pragma unroll 4
    for (int h = 0; h < 64; h++) {
        const float4* wr = (const float4*)(s_w1 + h * 32);   // broadcast LDS
        float a0 = 0.f, a1 = 0.f, a2 = 0.f, a3 = 0.f;
#pragma unroll
        for (int i = 0; i < 8; i++) {
            float4 wv = wr[i];
            a0 = fmaf(wv.x, xv[i].x, a0);
            a1 = fmaf(wv.y, xv[i].y, a1);
            a2 = fmaf(wv.z, xv[i].z, a2);
            a3 = fmaf(wv.w, xv[i].w, a3);
        }
        float hv = s_b1[h] + ((a0 + a1) + (a2 + a3));
        hv = fmaxf(hv, 0.0f);
        l0 = fmaf(s_w2[h], hv, l0);
        l1 = fmaf(s_w2[64 + h], hv, l1);
        l2 = fmaf(s_w2[128 + h], hv, l2);
    }

    int p = 0;
    float m = l0;
    if (l1 > m) { m = l1; p = 1; }   // strict > = first-max (jnp.argmax)
    if (l2 > m) { m = l2; p = 2; }

    // Pack: warp = one n (lane = window). Two ballots -> uint2.
    unsigned b0 = __ballot_sync(0xffffffffu, p & 1);
    unsigned bb1 = __ballot_sync(0xffffffffu, p & 2);
    if ((tid & 31) == 0) g_predpk[w >> 5] = make_uint2(b0, bb1);
}

// ---------------------------------------------------------------------------
// Kernel 2: embedding + repeat + PE + store.
// R9 mapping + two L1-instruction cuts:
//   (a) pred from packed ballot words (ALU) — no per-window LDS
//   (b) per-window 4x4 in-register warp transpose -> ONE STG.128 per thread
//       instead of 4 strided STG.32 (each of the 4 k-lines per warp is a
//       full coalesced 128B sector).
// ---------------------------------------------------------------------------
__global__ void __launch_bounds__(256, 2)
emb_kernel(const float* __restrict__ x,
           const float* __restrict__ we0,   // [512][8]
           const float* __restrict__ we1,   // [512][16]
           const float* __restrict__ we2,   // [512][32]
           float* __restrict__ out) {
    __shared__ __align__(16) float s_x[R_WIN * 32];   // 4 KB

    const int tid  = threadIdx.x;
    const int lane = tid & 31;
    const int wrp  = tid >> 5;
    const int n    = blockIdx.x >> 1;
    const int dblk = (blockIdx.x & 1) << 8;
    const int d    = dblk + tid;

    // Weight cache as packed pairs.
    u64 w0r[4], w1r[8], w2r[16];
    {
        const ulonglong2* p0 = (const ulonglong2*)(we0 + d * 8);
#pragma unroll
        for (int i = 0; i < 2; i++) { ulonglong2 v = p0[i]; w0r[2*i] = v.x; w0r[2*i+1] = v.y; }
        const ulonglong2* p1 = (const ulonglong2*)(we1 + d * 16);
#pragma unroll
        for (int i = 0; i < 4; i++) { ulonglong2 v = p1[i]; w1r[2*i] = v.x; w1r[2*i+1] = v.y; }
        const ulonglong2* p2 = (const ulonglong2*)(we2 + d * 32);
#pragma unroll
        for (int i = 0; i < 8; i++) { ulonglong2 v = p2[i]; w2r[2*i] = v.x; w2r[2*i+1] = v.y; }
    }

    // Cooperative x-row load + packed preds (converged broadcast LDG).
    {
        const float4* xg = (const float4*)(x + (size_t)n * 1024);
        ((float4*)s_x)[tid] = xg[tid];
    }
    const uint2 pb = g_predpk[n];

    // PE setup: step sines/cosines for k = 1..4 steps of Delta.
    const float kLn = -9.21034037197618f / (float)DM;   // -ln(10000)/512
    float delta = expf((float)(d & ~1) * kLn);
    float s1, c1;
    sincosf(delta, &s1, &c1);
    float s2 = 2.0f * s1 * c1;
    float c2 = fmaf(c1, c1, -s1 * s1);
    float s3 = fmaf(s1, c2, c1 * s2);
    float c3 = fmaf(c1, c2, -s1 * s2);
    float s4 = 2.0f * s2 * c2;
    float c4 = fmaf(c2, c2, -s2 * s2);
    // Phase-shifted state: odd d computes cos via sin(x + pi/2).
    float s = (d & 1) ? 1.0f : 0.0f;
    float c = (d & 1) ? 0.0f : 1.0f;

    __syncthreads();

    // Transposed store base: this lane writes k = lane&3, d-quad = 4*(lane>>2)
    // within its warp's 32-d span.
    float* ot = out + (size_t)n * (PE_LEN * DM)
              + (size_t)(lane & 3) * DM
              + dblk + wrp * 32 + ((lane >> 2) << 2);
    const bool f1 = lane & 1;
    const bool f2 = lane & 2;

#pragma unroll 1
    for (int w = 0; w < R_WIN; w++) {
        int pred = ((pb.x >> w) & 1u) | (((pb.y >> w) & 1u) << 1);

        const ulonglong2* xq2 = (const ulonglong2*)(s_x + w * 32);
        u64 xv[16];
#pragma unroll
        for (int i = 0; i < 8; i++) { ulonglong2 v = xq2[i]; xv[2*i] = v.x; xv[2*i+1] = v.y; }

        float v0, v1, v2, v3;
        if (pred == 0) {
            // 4 patches of 8 floats; repeat idx = [0,1,2,3]
            float acc[4];
#pragma unroll
            for (int k = 0; k < 4; k++) {
                u64 a = mul2(w0r[0], xv[4*k]);
                a = fma2(w0r[1], xv[4*k+1], a);
                a = fma2(w0r[2], xv[4*k+2], a);
                a = fma2(w0r[3], xv[4*k+3], a);
                acc[k] = hadd2(a);
            }
            v0 = acc[0]; v1 = acc[1]; v2 = acc[2]; v3 = acc[3];
        } else if (pred == 1) {
            // 2 patches of 16 floats; repeat idx = [0,0,0,1]
            u64 a0 = mul2(w1r[0], xv[0]);
            u64 a1 = mul2(w1r[1], xv[1]);
            a0 = fma2(w1r[2], xv[2], a0);
            a1 = fma2(w1r[3], xv[3], a1);
            a0 = fma2(w1r[4], xv[4], a0);
            a1 = fma2(w1r[5], xv[5], a1);
            a0 = fma2(w1r[6], xv[6], a0);
            a1 = fma2(w1r[7], xv[7], a1);
            float a = hadd2(add2(a0, a1));

            u64 b0 = mul2(w1r[0], xv[8]);
            u64 b1 = mul2(w1r[1], xv[9]);
            b0 = fma2(w1r[2], xv[10], b0);
            b1 = fma2(w1r[3], xv[11], b1);
            b0 = fma2(w1r[4], xv[12], b0);
            b1 = fma2(w1r[5], xv[13], b1);
            b0 = fma2(w1r[6], xv[14], b0);
            b1 = fma2(w1r[7], xv[15], b1);
            float b = hadd2(add2(b0, b1));
            v0 = a; v1 = a; v2 = a; v3 = b;
        } else {
            // 1 patch of 32 floats -> replicated 4x
            u64 a0 = mul2(w2r[0], xv[0]);
            u64 a1 = mul2(w2r[1], xv[1]);
            u64 a2 = mul2(w2r[2], xv[2]);
            u64 a3 = mul2(w2r[3], xv[3]);
#pragma unroll
            for (int i = 4; i < 16; i += 4) {
                a0 = fma2(w2r[i],   xv[i],   a0);
                a1 = fma2(w2r[i+1], xv[i+1], a1);
                a2 = fma2(w2r[i+2], xv[i+2], a2);
                a3 = fma2(w2r[i+3], xv[i+3], a3);
            }
            float cc = hadd2(add2(add2(a0, a1), add2(a2, a3)));
            v0 = cc; v1 = cc; v2 = cc; v3 = cc;
        }

        // Fold PE (independent rotations from the window-base angle).
        float y0 = v0 + s;
        float y1 = fmaf(s, c1, fmaf(c, s1, v1));
        float y2 = fmaf(s, c2, fmaf(c, s2, v2));
        float y3 = fmaf(s, c3, fmaf(c, s3, v3));
        // Advance base angle by 4*Delta.
        float ns = fmaf(s, c4, c * s4);
        c = fmaf(c, c4, -s * s4);
        s = ns;

        // 4x4 transpose within lane quads: after this, lane holds k=lane&3
        // for the 4 consecutive d's of its quad.
        {
            float sA = f1 ? y0 : y1;
            float sB = f1 ? y2 : y3;
            sA = __shfl_xor_sync(0xffffffffu, sA, 1);
            sB = __shfl_xor_sync(0xffffffffu, sB, 1);
            if (f1) { y0 = sA; y2 = sB; } else { y1 = sA; y3 = sB; }
            float sC = f2 ? y0 : y2;
            float sD = f2 ? y1 : y3;
            sC = __shfl_xor_sync(0xffffffffu, sC, 2);
            sD = __shfl_xor_sync(0xffffffffu, sD, 2);
            if (f2) { y0 = sC; y1 = sD; } else { y2 = sC; y3 = sD; }
        }

        *(float4*)ot = make_float4(y0, y1, y2, y3);
        ot += TGT * DM;
    }
}

extern "C" void kernel_launch(void* const* d_in, const int* in_sizes, int n_in,
                              void* d_out, int out_size) {
    const float* x   = (const float*)d_in[0];
    const float* w1  = (const float*)d_in[1];
    const float* b1  = (const float*)d_in[2];
    const float* w2  = (const float*)d_in[3];
    const float* b2  = (const float*)d_in[4];
    const float* we0 = (const float*)d_in[5];
    const float* we1 = (const float*)d_in[6];
    const float* we2 = (const float*)d_in[7];
    float* out = (float*)d_out;

    long long total = (long long)out_size;
    long long tail  = (total > MAIN_OUT) ? (total - MAIN_OUT) : 0;
    int tail_blocks = (int)((tail + 127) / 128);

    pre_kernel<<<CLS_BLOCKS + tail_blocks, 128>>>(x, w1, b1, w2, b2,
                                                  out, MAIN_OUT, total);
    emb_kernel<<<N_ROWS * 2, 256>>>(x, we0, we1, we2, out);
}